// round 15
// baseline (speedup 1.0000x reference)
#include <cuda_runtime.h>
#include <cuda_bf16.h>
#include <cstdint>

#define M_TOTAL 65536   // B*T = 512*128
#define C_DIM   384
#define H_DIM   64
#define T_DIM   128
#define B_DIM   512
#define ASTRIDE 40      // gemm smem row stride (bf16)
#define QSTR    72      // attn Q/K smem stride (bf16)
#define VSTR    136     // attn Vt smem stride (bf16)

// Pre-transposed, bf16 hi/lo split weights: [n=192][k=384]
__device__ __nv_bfloat16 g_wh[192 * C_DIM];
__device__ __nv_bfloat16 g_wl[192 * C_DIM];

__device__ __forceinline__ uint32_t smem_u32(const void* p) {
    uint32_t a;
    asm("{ .reg .u64 t; cvta.to.shared.u64 t, %1; cvt.u32.u64 %0, t; }"
        : "=r"(a) : "l"(p));
    return a;
}
#define CP_ASYNC16(dst, src) \
    asm volatile("cp.async.ca.shared.global [%0], [%1], 16;" \
                 :: "r"(dst), "l"(src) : "memory")
#define CP_COMMIT() asm volatile("cp.async.commit_group;" ::: "memory")
#define CP_WAIT0()  asm volatile("cp.async.wait_group 0;" ::: "memory")

// ---------------------------------------------------------------------------
// Kernel 0: convert W -> transposed bf16 hi/lo. n = plane*64 + h.
// ---------------------------------------------------------------------------
__global__ __launch_bounds__(256) void wconv_kernel(
    const float* __restrict__ Wq, const float* __restrict__ Wk,
    const float* __restrict__ Wv)
{
    int idx = blockIdx.x * 256 + threadIdx.x;
    if (idx >= 192 * C_DIM) return;
    int n = idx / C_DIM;
    int k = idx % C_DIM;
    int plane = n >> 6;
    int h = n & 63;
    const float* W = (plane == 0) ? Wq : (plane == 1) ? Wk : Wv;
    float v = W[k * H_DIM + h];
    __nv_bfloat16 hi = __float2bfloat16_rn(v);
    __nv_bfloat16 lo = __float2bfloat16_rn(v - __bfloat162float(hi));
    g_wh[n * C_DIM + k] = hi;
    g_wl[n * C_DIM + k] = lo;
}

// ---------------------------------------------------------------------------
// bf16 mma.sync m16n8k16 (row.col), fp32 accumulate
// ---------------------------------------------------------------------------
__device__ __forceinline__ void mma16816(float* c, const unsigned* a,
                                         unsigned b0, unsigned b1)
{
    asm volatile(
        "mma.sync.aligned.m16n8k16.row.col.f32.bf16.bf16.f32 "
        "{%0,%1,%2,%3}, {%4,%5,%6,%7}, {%8,%9}, {%0,%1,%2,%3};"
        : "+f"(c[0]), "+f"(c[1]), "+f"(c[2]), "+f"(c[3])
        : "r"(a[0]), "r"(a[1]), "r"(a[2]), "r"(a[3]), "r"(b0), "r"(b1));
}

// ===========================================================================
// Fused kernel: one CTA per batch. 2 CTAs/SM (reg cap 128, smem 108.5KB).
// Phase 1: QKV GEMM with cp.async pipeline: B (pre-split bf16) double-
//          buffered; A staged fp32->smem via cp.async, converted via LDS.
// Phase 2: causal attention on HMMA, SMSP-balanced warp->row-block remap.
// ===========================================================================
__global__ __launch_bounds__(256, 2) void fused_head(
    const float* __restrict__ x, float* __restrict__ out)
{
    extern __shared__ __nv_bfloat16 smb[];
    // ---- phase-1 layout ----
    __nv_bfloat16* Ah  = smb;                       // 128*40
    __nv_bfloat16* Al  = Ah + 128 * ASTRIDE;        // 128*40
    __nv_bfloat16* Bt  = Al + 128 * ASTRIDE;        // 2 bufs x (Bh,Bl) each 192*40
    float*         A32 = (float*)(Bt + 2 * 2 * 192 * ASTRIDE);   // 128*32 fp32
    // ---- phase-2 layout (same storage) ----
    __nv_bfloat16* Qh = smb;                        // [128][QSTR]
    __nv_bfloat16* Ql = Qh + 128 * QSTR;
    __nv_bfloat16* Kh = Ql + 128 * QSTR;
    __nv_bfloat16* Kl = Kh + 128 * QSTR;
    __nv_bfloat16* Vh = Kl + 128 * QSTR;            // transposed [64][VSTR]
    __nv_bfloat16* Vl = Vh + 64 * VSTR;

    const int tid  = threadIdx.x;
    const int warp = tid >> 5, lane = tid & 31;
    const int g = lane >> 2, ctg = lane & 3;
    const int b = blockIdx.x;
    const int m0 = b * 128;

    const uint32_t a32_s = smem_u32(A32);
    const uint32_t bt_s  = smem_u32(Bt);

    // ======================= Phase 1: QKV GEMM =======================
    const int wm = (warp & 3) * 32;
    const int wn = (warp >> 2) * 96;

    float acc[2][12][4];
    #pragma unroll
    for (int a = 0; a < 2; a++)
        #pragma unroll
        for (int bb = 0; bb < 12; bb++)
            #pragma unroll
            for (int c = 0; c < 4; c++) acc[a][bb][c] = 0.f;

    // ---- preload chunk 0 via cp.async ----
    {
        #pragma unroll
        for (int i = 0; i < 4; i++) {               // A32: 1024 x 16B chunks
            int idx = tid + (i << 8);
            int r = idx >> 3, c4 = (idx & 7) << 2;  // float4 col
            CP_ASYNC16(a32_s + (uint32_t)(r * 32 + c4) * 4,
                       x + (size_t)(m0 + r) * C_DIM + c4);
        }
        #pragma unroll
        for (int i = 0; i < 6; i++) {               // B: 1536 x 16B chunks
            int idx = tid + (i << 8);
            bool hi = idx < 768;
            int v = hi ? idx : idx - 768;
            int n = v >> 2, c8 = (v & 3) << 3;      // cols 0,8,16,24
            const __nv_bfloat16* src = (hi ? g_wh : g_wl) + n * C_DIM + c8;
            uint32_t dst = bt_s + (uint32_t)((hi ? 0 : 192 * ASTRIDE)
                                             + n * ASTRIDE + c8) * 2;
            CP_ASYNC16(dst, src);
        }
        CP_COMMIT();
    }

    for (int it = 0; it < 12; it++) {
        CP_WAIT0();
        __syncthreads();

        // ---- convert A32 -> Ah/Al (smem to smem) ----
        #pragma unroll
        for (int i = 0; i < 4; i++) {
            int idx = tid + (i << 8);
            int r = idx >> 3, kq = (idx & 7) << 2;
            float4 a = *(const float4*)&A32[r * 32 + kq];
            __nv_bfloat162 h0 = __floats2bfloat162_rn(a.x, a.y);
            __nv_bfloat162 h1 = __floats2bfloat162_rn(a.z, a.w);
            __nv_bfloat162 l0 = __floats2bfloat162_rn(a.x - __low2float(h0),
                                                      a.y - __high2float(h0));
            __nv_bfloat162 l1 = __floats2bfloat162_rn(a.z - __low2float(h1),
                                                      a.w - __high2float(h1));
            *(__nv_bfloat162*)&Ah[r * ASTRIDE + kq]     = h0;
            *(__nv_bfloat162*)&Ah[r * ASTRIDE + kq + 2] = h1;
            *(__nv_bfloat162*)&Al[r * ASTRIDE + kq]     = l0;
            *(__nv_bfloat162*)&Al[r * ASTRIDE + kq + 2] = l1;
        }
        __syncthreads();

        // ---- issue next chunk's copies (overlap with compute) ----
        if (it + 1 < 12) {
            const int k0n = (it + 1) * 32;
            const int nb = (it + 1) & 1;
            #pragma unroll
            for (int i = 0; i < 4; i++) {
                int idx = tid + (i << 8);
                int r = idx >> 3, c4 = (idx & 7) << 2;
                CP_ASYNC16(a32_s + (uint32_t)(r * 32 + c4) * 4,
                           x + (size_t)(m0 + r) * C_DIM + k0n + c4);
            }
            #pragma unroll
            for (int i = 0; i < 6; i++) {
                int idx = tid + (i << 8);
                bool hi = idx < 768;
                int v = hi ? idx : idx - 768;
                int n = v >> 2, c8 = (v & 3) << 3;
                const __nv_bfloat16* src = (hi ? g_wh : g_wl) + n * C_DIM + k0n + c8;
                uint32_t dst = bt_s + (uint32_t)(nb * 2 * 192 * ASTRIDE
                                                 + (hi ? 0 : 192 * ASTRIDE)
                                                 + n * ASTRIDE + c8) * 2;
                CP_ASYNC16(dst, src);
            }
            CP_COMMIT();
        }

        // ---- compute on buffer it&1 ----
        const __nv_bfloat16* Bh = Bt + (it & 1) * 2 * 192 * ASTRIDE;
        const __nv_bfloat16* Bl = Bh + 192 * ASTRIDE;
        #pragma unroll
        for (int ks = 0; ks < 2; ks++) {
            const int kb = ks * 16;
            unsigned ah[2][4], al[2][4];
            #pragma unroll
            for (int mt = 0; mt < 2; mt++) {
                int r = wm + mt * 16 + g;
                int c = kb + ctg * 2;
                ah[mt][0] = *(const unsigned*)&Ah[r * ASTRIDE + c];
                ah[mt][1] = *(const unsigned*)&Ah[(r + 8) * ASTRIDE + c];
                ah[mt][2] = *(const unsigned*)&Ah[r * ASTRIDE + c + 8];
                ah[mt][3] = *(const unsigned*)&Ah[(r + 8) * ASTRIDE + c + 8];
                al[mt][0] = *(const unsigned*)&Al[r * ASTRIDE + c];
                al[mt][1] = *(const unsigned*)&Al[(r + 8) * ASTRIDE + c];
                al[mt][2] = *(const unsigned*)&Al[r * ASTRIDE + c + 8];
                al[mt][3] = *(const unsigned*)&Al[(r + 8) * ASTRIDE + c + 8];
            }
            #pragma unroll
            for (int nt = 0; nt < 12; nt++) {
                int n = wn + nt * 8 + g;
                int c = kb + ctg * 2;
                unsigned bh0 = *(const unsigned*)&Bh[n * ASTRIDE + c];
                unsigned bh1 = *(const unsigned*)&Bh[n * ASTRIDE + c + 8];
                unsigned bl0 = *(const unsigned*)&Bl[n * ASTRIDE + c];
                unsigned bl1 = *(const unsigned*)&Bl[n * ASTRIDE + c + 8];
                #pragma unroll
                for (int mt = 0; mt < 2; mt++) {
                    mma16816(acc[mt][nt], ah[mt], bh0, bh1);
                    mma16816(acc[mt][nt], ah[mt], bl0, bl1);
                    mma16816(acc[mt][nt], al[mt], bh0, bh1);
                }
            }
        }
        __syncthreads();
    }

    // ---- epilogue: split hi/lo and write DIRECTLY into attention layouts ----
    #pragma unroll
    for (int mt = 0; mt < 2; mt++)
        #pragma unroll
        for (int nt = 0; nt < 12; nt++) {
            int r0 = wm + mt * 16 + g;
            int n = wn + nt * 8 + ctg * 2;
            #pragma unroll
            for (int half = 0; half < 2; half++) {
                int r = half ? (r0 + 8) : r0;
                float c0 = acc[mt][nt][half * 2 + 0];
                float c1 = acc[mt][nt][half * 2 + 1];
                __nv_bfloat162 h2 = __floats2bfloat162_rn(c0, c1);
                __nv_bfloat162 l2 = __floats2bfloat162_rn(c0 - __low2float(h2),
                                                          c1 - __high2float(h2));
                if (n < 64) {
                    *(__nv_bfloat162*)&Qh[r * QSTR + n] = h2;
                    *(__nv_bfloat162*)&Ql[r * QSTR + n] = l2;
                } else if (n < 128) {
                    *(__nv_bfloat162*)&Kh[r * QSTR + (n - 64)] = h2;
                    *(__nv_bfloat162*)&Kl[r * QSTR + (n - 64)] = l2;
                } else {
                    int h = n - 128;
                    Vh[h * VSTR + r]       = h2.x;
                    Vh[(h + 1) * VSTR + r] = h2.y;
                    Vl[h * VSTR + r]       = l2.x;
                    Vl[(h + 1) * VSTR + r] = l2.y;
                }
            }
        }
    __syncthreads();

    // ======================= Phase 2: attention =======================
    // SMSP-balanced remap: warp w handles row-block p; pairs (7-w, w-4)
    // put cost {16,2},{14,4},{12,6},{10,8} on each SMSP -> all equal.
    const int p = (warp < 4) ? (7 - warp) : (warp - 4);
    const int am0 = p * 16;
    const int ntmax = 2 * p + 1;
    const float scale = 0.40824829046386301636f;   // 6^-0.5
    const float NEG = -1e30f;

    float S[16][4];
    #pragma unroll
    for (int nt = 0; nt < 16; nt++)
        #pragma unroll
        for (int j = 0; j < 4; j++) S[nt][j] = 0.f;

    #pragma unroll 1
    for (int kt = 0; kt < 4; kt++) {
        const int kc = kt * 16 + ctg * 2;
        unsigned ah[4], al[4];
        ah[0] = *(const unsigned*)&Qh[(am0 + g) * QSTR + kc];
        ah[1] = *(const unsigned*)&Qh[(am0 + 8 + g) * QSTR + kc];
        ah[2] = *(const unsigned*)&Qh[(am0 + g) * QSTR + kc + 8];
        ah[3] = *(const unsigned*)&Qh[(am0 + 8 + g) * QSTR + kc + 8];
        al[0] = *(const unsigned*)&Ql[(am0 + g) * QSTR + kc];
        al[1] = *(const unsigned*)&Ql[(am0 + 8 + g) * QSTR + kc];
        al[2] = *(const unsigned*)&Ql[(am0 + g) * QSTR + kc + 8];
        al[3] = *(const unsigned*)&Ql[(am0 + 8 + g) * QSTR + kc + 8];
        #pragma unroll
        for (int nt = 0; nt < 16; nt++) {
            if (nt <= ntmax) {
                unsigned bh0 = *(const unsigned*)&Kh[(nt * 8 + g) * QSTR + kc];
                unsigned bh1 = *(const unsigned*)&Kh[(nt * 8 + g) * QSTR + kc + 8];
                unsigned bl0 = *(const unsigned*)&Kl[(nt * 8 + g) * QSTR + kc];
                unsigned bl1 = *(const unsigned*)&Kl[(nt * 8 + g) * QSTR + kc + 8];
                mma16816(S[nt], ah, bh0, bh1);
                mma16816(S[nt], ah, bl0, bl1);
                mma16816(S[nt], al, bh0, bh1);
            }
        }
    }

    const int t1 = am0 + g, t2 = am0 + 8 + g;
    float mx1 = NEG, mx2 = NEG;
    #pragma unroll
    for (int nt = 0; nt < 16; nt++) {
        if (nt <= ntmax) {
            int s0 = nt * 8 + ctg * 2;
            S[nt][0] = (s0     <= t1) ? S[nt][0] * scale : NEG;
            S[nt][1] = (s0 + 1 <= t1) ? S[nt][1] * scale : NEG;
            S[nt][2] = (s0     <= t2) ? S[nt][2] * scale : NEG;
            S[nt][3] = (s0 + 1 <= t2) ? S[nt][3] * scale : NEG;
            mx1 = fmaxf(mx1, fmaxf(S[nt][0], S[nt][1]));
            mx2 = fmaxf(mx2, fmaxf(S[nt][2], S[nt][3]));
        }
    }
    mx1 = fmaxf(mx1, __shfl_xor_sync(0xffffffffu, mx1, 1));
    mx1 = fmaxf(mx1, __shfl_xor_sync(0xffffffffu, mx1, 2));
    mx2 = fmaxf(mx2, __shfl_xor_sync(0xffffffffu, mx2, 1));
    mx2 = fmaxf(mx2, __shfl_xor_sync(0xffffffffu, mx2, 2));

    float sum1 = 0.f, sum2 = 0.f;
    #pragma unroll
    for (int nt = 0; nt < 16; nt++) {
        if (nt <= ntmax) {
            S[nt][0] = __expf(S[nt][0] - mx1);
            S[nt][1] = __expf(S[nt][1] - mx1);
            S[nt][2] = __expf(S[nt][2] - mx2);
            S[nt][3] = __expf(S[nt][3] - mx2);
            sum1 += S[nt][0] + S[nt][1];
            sum2 += S[nt][2] + S[nt][3];
        }
    }
    sum1 += __shfl_xor_sync(0xffffffffu, sum1, 1);
    sum1 += __shfl_xor_sync(0xffffffffu, sum1, 2);
    sum2 += __shfl_xor_sync(0xffffffffu, sum2, 1);
    sum2 += __shfl_xor_sync(0xffffffffu, sum2, 2);
    const float inv1 = __frcp_rn(sum1), inv2 = __frcp_rn(sum2);

    #pragma unroll
    for (int nt = 0; nt < 16; nt++) {
        if (nt <= ntmax) {
            S[nt][0] *= inv1;
            S[nt][1] *= inv1;
            S[nt][2] *= inv2;
            S[nt][3] *= inv2;
        }
    }

    float O[8][4];
    #pragma unroll
    for (int nt2 = 0; nt2 < 8; nt2++)
        #pragma unroll
        for (int j = 0; j < 4; j++) O[nt2][j] = 0.f;

    #pragma unroll
    for (int kt2 = 0; kt2 < 8; kt2++) {
        if (kt2 <= p) {
            unsigned wah[4], wal[4];
            __nv_bfloat162 h2, l2;
            h2 = __floats2bfloat162_rn(S[2 * kt2][0], S[2 * kt2][1]);
            l2 = __floats2bfloat162_rn(S[2 * kt2][0] - __low2float(h2),
                                       S[2 * kt2][1] - __high2float(h2));
            wah[0] = *(unsigned*)&h2; wal[0] = *(unsigned*)&l2;
            h2 = __floats2bfloat162_rn(S[2 * kt2][2], S[2 * kt2][3]);
            l2 = __floats2bfloat162_rn(S[2 * kt2][2] - __low2float(h2),
                                       S[2 * kt2][3] - __high2float(h2));
            wah[1] = *(unsigned*)&h2; wal[1] = *(unsigned*)&l2;
            h2 = __floats2bfloat162_rn(S[2 * kt2 + 1][0], S[2 * kt2 + 1][1]);
            l2 = __floats2bfloat162_rn(S[2 * kt2 + 1][0] - __low2float(h2),
                                       S[2 * kt2 + 1][1] - __high2float(h2));
            wah[2] = *(unsigned*)&h2; wal[2] = *(unsigned*)&l2;
            h2 = __floats2bfloat162_rn(S[2 * kt2 + 1][2], S[2 * kt2 + 1][3]);
            l2 = __floats2bfloat162_rn(S[2 * kt2 + 1][2] - __low2float(h2),
                                       S[2 * kt2 + 1][3] - __high2float(h2));
            wah[3] = *(unsigned*)&h2; wal[3] = *(unsigned*)&l2;

            const int kc = kt2 * 16 + ctg * 2;
            #pragma unroll
            for (int nt2 = 0; nt2 < 8; nt2++) {
                unsigned bh0 = *(const unsigned*)&Vh[(nt2 * 8 + g) * VSTR + kc];
                unsigned bh1 = *(const unsigned*)&Vh[(nt2 * 8 + g) * VSTR + kc + 8];
                unsigned bl0 = *(const unsigned*)&Vl[(nt2 * 8 + g) * VSTR + kc];
                unsigned bl1 = *(const unsigned*)&Vl[(nt2 * 8 + g) * VSTR + kc + 8];
                mma16816(O[nt2], wah, bh0, bh1);
                mma16816(O[nt2], wah, bl0, bl1);
                mma16816(O[nt2], wal, bh0, bh1);
            }
        }
    }

    float* ob = out + (size_t)b * T_DIM * H_DIM;
    #pragma unroll
    for (int nt2 = 0; nt2 < 8; nt2++) {
        int h0 = nt2 * 8 + ctg * 2;
        *(float2*)(ob + (size_t)t1 * H_DIM + h0) = make_float2(O[nt2][0], O[nt2][1]);
        *(float2*)(ob + (size_t)t2 * H_DIM + h0) = make_float2(O[nt2][2], O[nt2][3]);
    }
}

// ---------------------------------------------------------------------------
extern "C" void kernel_launch(void* const* d_in, const int* in_sizes, int n_in,
                              void* d_out, int out_size)
{
    const float* x  = (const float*)d_in[0];
    const float* Wq = (const float*)d_in[1];
    const float* Wk = (const float*)d_in[2];
    const float* Wv = (const float*)d_in[3];
    float* out = (float*)d_out;

    wconv_kernel<<<(192 * C_DIM + 255) / 256, 256>>>(Wq, Wk, Wv);

    int fsmem = (4 * 128 * QSTR + 2 * 64 * VSTR) * (int)sizeof(__nv_bfloat16);  // 108544
    cudaFuncSetAttribute(fused_head, cudaFuncAttributeMaxDynamicSharedMemorySize, fsmem);
    fused_head<<<B_DIM, 256, fsmem>>>(x, out);
}

// round 16
// speedup vs baseline: 1.2199x; 1.2199x over previous
#include <cuda_runtime.h>
#include <cuda_bf16.h>
#include <cstdint>

#define M_TOTAL 65536   // B*T = 512*128
#define C_DIM   384
#define H_DIM   64
#define T_DIM   128
#define B_DIM   512
#define ASTRIDE 40      // gemm smem row stride (bf16)
#define QSTR    72      // attn Q/K smem stride (bf16)
#define VSTR    136     // attn Vt smem stride (bf16)

// Pre-transposed, bf16 hi/lo split weights: [n=192][k=384]
__device__ __nv_bfloat16 g_wh[192 * C_DIM];
__device__ __nv_bfloat16 g_wl[192 * C_DIM];

// ---------------------------------------------------------------------------
// Kernel 0: convert W -> transposed bf16 hi/lo. n = plane*64 + h.
// ---------------------------------------------------------------------------
__global__ __launch_bounds__(256) void wconv_kernel(
    const float* __restrict__ Wq, const float* __restrict__ Wk,
    const float* __restrict__ Wv)
{
    int idx = blockIdx.x * 256 + threadIdx.x;
    if (idx >= 192 * C_DIM) return;
    int n = idx / C_DIM;
    int k = idx % C_DIM;
    int plane = n >> 6;
    int h = n & 63;
    const float* W = (plane == 0) ? Wq : (plane == 1) ? Wk : Wv;
    float v = W[k * H_DIM + h];
    __nv_bfloat16 hi = __float2bfloat16_rn(v);
    __nv_bfloat16 lo = __float2bfloat16_rn(v - __bfloat162float(hi));
    g_wh[n * C_DIM + k] = hi;
    g_wl[n * C_DIM + k] = lo;
}

// ---------------------------------------------------------------------------
// bf16 mma.sync m16n8k16 (row.col), fp32 accumulate
// ---------------------------------------------------------------------------
__device__ __forceinline__ void mma16816(float* c, const unsigned* a,
                                         unsigned b0, unsigned b1)
{
    asm volatile(
        "mma.sync.aligned.m16n8k16.row.col.f32.bf16.bf16.f32 "
        "{%0,%1,%2,%3}, {%4,%5,%6,%7}, {%8,%9}, {%0,%1,%2,%3};"
        : "+f"(c[0]), "+f"(c[1]), "+f"(c[2]), "+f"(c[3])
        : "r"(a[0]), "r"(a[1]), "r"(a[2]), "r"(a[3]), "r"(b0), "r"(b1));
}

// ===========================================================================
// Fused kernel: one CTA per batch. 2 CTAs/SM (reg cap 128, smem 108.5KB).
// Phase 1: QKV GEMM, direct loads (R12-proven: occupancy hides LDG latency).
// Phase 2: causal attention on HMMA, SMSP-balanced warp->row-block remap.
// ===========================================================================
__global__ __launch_bounds__(256, 2) void fused_head(
    const float* __restrict__ x, float* __restrict__ out)
{
    extern __shared__ __nv_bfloat16 smb[];
    // phase-1 aliases
    __nv_bfloat16* Ah = smb;                 // 128*40
    __nv_bfloat16* Al = Ah + 128 * ASTRIDE;
    __nv_bfloat16* Bh = Al + 128 * ASTRIDE;  // 192*40
    __nv_bfloat16* Bl = Bh + 192 * ASTRIDE;
    // phase-2 aliases (same storage, larger footprint)
    __nv_bfloat16* Qh = smb;                 // [128][QSTR]
    __nv_bfloat16* Ql = Qh + 128 * QSTR;
    __nv_bfloat16* Kh = Ql + 128 * QSTR;
    __nv_bfloat16* Kl = Kh + 128 * QSTR;
    __nv_bfloat16* Vh = Kl + 128 * QSTR;     // transposed [64][VSTR]
    __nv_bfloat16* Vl = Vh + 64 * VSTR;

    const int tid  = threadIdx.x;
    const int warp = tid >> 5, lane = tid & 31;
    const int g = lane >> 2, ctg = lane & 3;
    const int b = blockIdx.x;
    const int m0 = b * 128;

    // ======================= Phase 1: QKV GEMM =======================
    const int wm = (warp & 3) * 32;          // 4 warps along m
    const int wn = (warp >> 2) * 96;         // 2 warps along n

    float acc[2][12][4];
    #pragma unroll
    for (int a = 0; a < 2; a++)
        #pragma unroll
        for (int bb = 0; bb < 12; bb++)
            #pragma unroll
            for (int c = 0; c < 4; c++) acc[a][bb][c] = 0.f;

    for (int it = 0; it < C_DIM / 32; it++) {
        const int k0 = it * 32;
        // A tile: load fp32, split hi/lo, store smem
        #pragma unroll
        for (int i = 0; i < 4; i++) {
            int v = tid + (i << 8);
            int m = v >> 3, kq = (v & 7) << 2;
            float4 a = *(const float4*)(x + (size_t)(m0 + m) * C_DIM + k0 + kq);
            __nv_bfloat162 h0 = __floats2bfloat162_rn(a.x, a.y);
            __nv_bfloat162 h1 = __floats2bfloat162_rn(a.z, a.w);
            __nv_bfloat162 l0 = __floats2bfloat162_rn(a.x - __low2float(h0),
                                                      a.y - __high2float(h0));
            __nv_bfloat162 l1 = __floats2bfloat162_rn(a.z - __low2float(h1),
                                                      a.w - __high2float(h1));
            *(__nv_bfloat162*)&Ah[m * ASTRIDE + kq]     = h0;
            *(__nv_bfloat162*)&Ah[m * ASTRIDE + kq + 2] = h1;
            *(__nv_bfloat162*)&Al[m * ASTRIDE + kq]     = l0;
            *(__nv_bfloat162*)&Al[m * ASTRIDE + kq + 2] = l1;
        }
        // B tiles (pre-split in gmem)
        #pragma unroll
        for (int i = 0; i < 6; i++) {
            int v = tid + (i << 8);
            int buf = (v >= 768);
            int vv = v - buf * 768;
            int n = vv >> 2, kq8 = (vv & 3) << 3;
            const __nv_bfloat16* src = (buf ? g_wl : g_wh) + n * C_DIM + k0 + kq8;
            *(uint4*)&(buf ? Bl : Bh)[n * ASTRIDE + kq8] = *(const uint4*)src;
        }
        __syncthreads();

        #pragma unroll
        for (int ks = 0; ks < 2; ks++) {
            const int kb = ks * 16;
            unsigned ah[2][4], al[2][4];
            #pragma unroll
            for (int mt = 0; mt < 2; mt++) {
                int r = wm + mt * 16 + g;
                int c = kb + ctg * 2;
                ah[mt][0] = *(const unsigned*)&Ah[r * ASTRIDE + c];
                ah[mt][1] = *(const unsigned*)&Ah[(r + 8) * ASTRIDE + c];
                ah[mt][2] = *(const unsigned*)&Ah[r * ASTRIDE + c + 8];
                ah[mt][3] = *(const unsigned*)&Ah[(r + 8) * ASTRIDE + c + 8];
                al[mt][0] = *(const unsigned*)&Al[r * ASTRIDE + c];
                al[mt][1] = *(const unsigned*)&Al[(r + 8) * ASTRIDE + c];
                al[mt][2] = *(const unsigned*)&Al[r * ASTRIDE + c + 8];
                al[mt][3] = *(const unsigned*)&Al[(r + 8) * ASTRIDE + c + 8];
            }
            #pragma unroll
            for (int nt = 0; nt < 12; nt++) {
                int n = wn + nt * 8 + g;
                int c = kb + ctg * 2;
                unsigned bh0 = *(const unsigned*)&Bh[n * ASTRIDE + c];
                unsigned bh1 = *(const unsigned*)&Bh[n * ASTRIDE + c + 8];
                unsigned bl0 = *(const unsigned*)&Bl[n * ASTRIDE + c];
                unsigned bl1 = *(const unsigned*)&Bl[n * ASTRIDE + c + 8];
                #pragma unroll
                for (int mt = 0; mt < 2; mt++) {
                    mma16816(acc[mt][nt], ah[mt], bh0, bh1);
                    mma16816(acc[mt][nt], ah[mt], bl0, bl1);
                    mma16816(acc[mt][nt], al[mt], bh0, bh1);
                }
            }
        }
        __syncthreads();
    }

    // ---- epilogue: split hi/lo and write DIRECTLY into attention layouts ----
    #pragma unroll
    for (int mt = 0; mt < 2; mt++)
        #pragma unroll
        for (int nt = 0; nt < 12; nt++) {
            int r0 = wm + mt * 16 + g;
            int n = wn + nt * 8 + ctg * 2;
            #pragma unroll
            for (int half = 0; half < 2; half++) {
                int r = half ? (r0 + 8) : r0;
                float c0 = acc[mt][nt][half * 2 + 0];
                float c1 = acc[mt][nt][half * 2 + 1];
                __nv_bfloat162 h2 = __floats2bfloat162_rn(c0, c1);
                __nv_bfloat162 l2 = __floats2bfloat162_rn(c0 - __low2float(h2),
                                                          c1 - __high2float(h2));
                if (n < 64) {
                    *(__nv_bfloat162*)&Qh[r * QSTR + n] = h2;
                    *(__nv_bfloat162*)&Ql[r * QSTR + n] = l2;
                } else if (n < 128) {
                    *(__nv_bfloat162*)&Kh[r * QSTR + (n - 64)] = h2;
                    *(__nv_bfloat162*)&Kl[r * QSTR + (n - 64)] = l2;
                } else {
                    int h = n - 128;
                    Vh[h * VSTR + r]       = h2.x;
                    Vh[(h + 1) * VSTR + r] = h2.y;
                    Vl[h * VSTR + r]       = l2.x;
                    Vl[(h + 1) * VSTR + r] = l2.y;
                }
            }
        }
    __syncthreads();

    // ======================= Phase 2: attention =======================
    // SMSP-balanced remap: warp w handles row-block p; pairs (7-w, w-4)
    // put cost {16,2},{14,4},{12,6},{10,8} on each SMSP -> all equal.
    const int p = (warp < 4) ? (7 - warp) : (warp - 4);
    const int am0 = p * 16;
    const int ntmax = 2 * p + 1;
    const float scale = 0.40824829046386301636f;   // 6^-0.5
    const float NEG = -1e30f;

    float S[16][4];
    #pragma unroll
    for (int nt = 0; nt < 16; nt++)
        #pragma unroll
        for (int j = 0; j < 4; j++) S[nt][j] = 0.f;

    #pragma unroll 1
    for (int kt = 0; kt < 4; kt++) {
        const int kc = kt * 16 + ctg * 2;
        unsigned ah[4], al[4];
        ah[0] = *(const unsigned*)&Qh[(am0 + g) * QSTR + kc];
        ah[1] = *(const unsigned*)&Qh[(am0 + 8 + g) * QSTR + kc];
        ah[2] = *(const unsigned*)&Qh[(am0 + g) * QSTR + kc + 8];
        ah[3] = *(const unsigned*)&Qh[(am0 + 8 + g) * QSTR + kc + 8];
        al[0] = *(const unsigned*)&Ql[(am0 + g) * QSTR + kc];
        al[1] = *(const unsigned*)&Ql[(am0 + 8 + g) * QSTR + kc];
        al[2] = *(const unsigned*)&Ql[(am0 + g) * QSTR + kc + 8];
        al[3] = *(const unsigned*)&Ql[(am0 + 8 + g) * QSTR + kc + 8];
        #pragma unroll
        for (int nt = 0; nt < 16; nt++) {
            if (nt <= ntmax) {
                unsigned bh0 = *(const unsigned*)&Kh[(nt * 8 + g) * QSTR + kc];
                unsigned bh1 = *(const unsigned*)&Kh[(nt * 8 + g) * QSTR + kc + 8];
                unsigned bl0 = *(const unsigned*)&Kl[(nt * 8 + g) * QSTR + kc];
                unsigned bl1 = *(const unsigned*)&Kl[(nt * 8 + g) * QSTR + kc + 8];
                mma16816(S[nt], ah, bh0, bh1);
                mma16816(S[nt], ah, bl0, bl1);
                mma16816(S[nt], al, bh0, bh1);
            }
        }
    }

    const int t1 = am0 + g, t2 = am0 + 8 + g;
    float mx1 = NEG, mx2 = NEG;
    #pragma unroll
    for (int nt = 0; nt < 16; nt++) {
        if (nt <= ntmax) {
            int s0 = nt * 8 + ctg * 2;
            S[nt][0] = (s0     <= t1) ? S[nt][0] * scale : NEG;
            S[nt][1] = (s0 + 1 <= t1) ? S[nt][1] * scale : NEG;
            S[nt][2] = (s0     <= t2) ? S[nt][2] * scale : NEG;
            S[nt][3] = (s0 + 1 <= t2) ? S[nt][3] * scale : NEG;
            mx1 = fmaxf(mx1, fmaxf(S[nt][0], S[nt][1]));
            mx2 = fmaxf(mx2, fmaxf(S[nt][2], S[nt][3]));
        }
    }
    mx1 = fmaxf(mx1, __shfl_xor_sync(0xffffffffu, mx1, 1));
    mx1 = fmaxf(mx1, __shfl_xor_sync(0xffffffffu, mx1, 2));
    mx2 = fmaxf(mx2, __shfl_xor_sync(0xffffffffu, mx2, 1));
    mx2 = fmaxf(mx2, __shfl_xor_sync(0xffffffffu, mx2, 2));

    float sum1 = 0.f, sum2 = 0.f;
    #pragma unroll
    for (int nt = 0; nt < 16; nt++) {
        if (nt <= ntmax) {
            S[nt][0] = __expf(S[nt][0] - mx1);
            S[nt][1] = __expf(S[nt][1] - mx1);
            S[nt][2] = __expf(S[nt][2] - mx2);
            S[nt][3] = __expf(S[nt][3] - mx2);
            sum1 += S[nt][0] + S[nt][1];
            sum2 += S[nt][2] + S[nt][3];
        }
    }
    sum1 += __shfl_xor_sync(0xffffffffu, sum1, 1);
    sum1 += __shfl_xor_sync(0xffffffffu, sum1, 2);
    sum2 += __shfl_xor_sync(0xffffffffu, sum2, 1);
    sum2 += __shfl_xor_sync(0xffffffffu, sum2, 2);
    const float inv1 = __frcp_rn(sum1), inv2 = __frcp_rn(sum2);

    // pre-normalize weights in place (masked entries are exactly 0)
    #pragma unroll
    for (int nt = 0; nt < 16; nt++) {
        if (nt <= ntmax) {
            S[nt][0] *= inv1;
            S[nt][1] *= inv1;
            S[nt][2] *= inv2;
            S[nt][3] *= inv2;
        }
    }

    float O[8][4];
    #pragma unroll
    for (int nt2 = 0; nt2 < 8; nt2++)
        #pragma unroll
        for (int j = 0; j < 4; j++) O[nt2][j] = 0.f;

    // AV: convert W fragments on the fly
    #pragma unroll
    for (int kt2 = 0; kt2 < 8; kt2++) {
        if (kt2 <= p) {
            unsigned wah[4], wal[4];
            __nv_bfloat162 h2, l2;
            h2 = __floats2bfloat162_rn(S[2 * kt2][0], S[2 * kt2][1]);
            l2 = __floats2bfloat162_rn(S[2 * kt2][0] - __low2float(h2),
                                       S[2 * kt2][1] - __high2float(h2));
            wah[0] = *(unsigned*)&h2; wal[0] = *(unsigned*)&l2;
            h2 = __floats2bfloat162_rn(S[2 * kt2][2], S[2 * kt2][3]);
            l2 = __floats2bfloat162_rn(S[2 * kt2][2] - __low2float(h2),
                                       S[2 * kt2][3] - __high2float(h2));
            wah[1] = *(unsigned*)&h2; wal[1] = *(unsigned*)&l2;
            h2 = __floats2bfloat162_rn(S[2 * kt2 + 1][0], S[2 * kt2 + 1][1]);
            l2 = __floats2bfloat162_rn(S[2 * kt2 + 1][0] - __low2float(h2),
                                       S[2 * kt2 + 1][1] - __high2float(h2));
            wah[2] = *(unsigned*)&h2; wal[2] = *(unsigned*)&l2;
            h2 = __floats2bfloat162_rn(S[2 * kt2 + 1][2], S[2 * kt2 + 1][3]);
            l2 = __floats2bfloat162_rn(S[2 * kt2 + 1][2] - __low2float(h2),
                                       S[2 * kt2 + 1][3] - __high2float(h2));
            wah[3] = *(unsigned*)&h2; wal[3] = *(unsigned*)&l2;

            const int kc = kt2 * 16 + ctg * 2;
            #pragma unroll
            for (int nt2 = 0; nt2 < 8; nt2++) {
                unsigned bh0 = *(const unsigned*)&Vh[(nt2 * 8 + g) * VSTR + kc];
                unsigned bh1 = *(const unsigned*)&Vh[(nt2 * 8 + g) * VSTR + kc + 8];
                unsigned bl0 = *(const unsigned*)&Vl[(nt2 * 8 + g) * VSTR + kc];
                unsigned bl1 = *(const unsigned*)&Vl[(nt2 * 8 + g) * VSTR + kc + 8];
                mma16816(O[nt2], wah, bh0, bh1);
                mma16816(O[nt2], wah, bl0, bl1);
                mma16816(O[nt2], wal, bh0, bh1);
            }
        }
    }

    float* ob = out + (size_t)b * T_DIM * H_DIM;
    #pragma unroll
    for (int nt2 = 0; nt2 < 8; nt2++) {
        int h0 = nt2 * 8 + ctg * 2;
        *(float2*)(ob + (size_t)t1 * H_DIM + h0) = make_float2(O[nt2][0], O[nt2][1]);
        *(float2*)(ob + (size_t)t2 * H_DIM + h0) = make_float2(O[nt2][2], O[nt2][3]);
    }
}

// ---------------------------------------------------------------------------
extern "C" void kernel_launch(void* const* d_in, const int* in_sizes, int n_in,
                              void* d_out, int out_size)
{
    const float* x  = (const float*)d_in[0];
    const float* Wq = (const float*)d_in[1];
    const float* Wk = (const float*)d_in[2];
    const float* Wv = (const float*)d_in[3];
    float* out = (float*)d_out;

    wconv_kernel<<<(192 * C_DIM + 255) / 256, 256>>>(Wq, Wk, Wv);

    int fsmem = (4 * 128 * QSTR + 2 * 64 * VSTR) * (int)sizeof(__nv_bfloat16);  // 108544
    cudaFuncSetAttribute(fused_head, cudaFuncAttributeMaxDynamicSharedMemorySize, fsmem);
    fused_head<<<B_DIM, 256, fsmem>>>(x, out);
}